// round 3
// baseline (speedup 1.0000x reference)
#include <cuda_runtime.h>

#define TT 128
#define BB 64
#define HH 128
#define EE0 128
#define EE1 64
#define TB (TT*BB)
#define LOG2E 1.4426950408889634f

// Scratch (device globals: no allocation allowed in kernel_launch)
__device__ float g_ms[TT*BB*HH];    // running mean  [T,B,H]
__device__ float g_x1T[BB*HH*TT];   // x1 transposed [B,H,T]
__device__ float g_q[TT*BB*HH];     // x2 + wms      [T,B,H]
__device__ float g_ma[TT*BB*HH];    // m_a           [T,B,H]

__device__ __forceinline__ float fex2(float x){ float r; asm("ex2.approx.f32 %0, %1;" : "=f"(r) : "f"(x)); return r; }
__device__ __forceinline__ float frcp(float x){ float r; asm("rcp.approx.f32 %0, %1;" : "=f"(r) : "f"(x)); return r; }
__device__ __forceinline__ float ftanh(float x){ float r; asm("tanh.approx.f32 %0, %1;" : "=f"(r) : "f"(x)); return r; }
__device__ __forceinline__ float sigmoidf_(float x){ return frcp(1.0f + fex2(x * -LOG2E)); }
__device__ __forceinline__ float leakyf_(float x){ return x > 0.0f ? x : 0.3f * x; }

// ---------------------------------------------------------------------------
// K1: running mean over time prefix. 8192 threads = (b,h); coalesced in h.
// ---------------------------------------------------------------------------
__global__ __launch_bounds__(128) void k_cumsum(const float* __restrict__ in) {
    int idx = blockIdx.x * 128 + threadIdx.x;   // b*H + h
    float acc = 0.0f;
#pragma unroll 4
    for (int t = 0; t < TT; t++) {
        acc += in[t * (BB*HH) + idx];
        g_ms[t * (BB*HH) + idx] = acc / (float)(t + 1);
    }
}

// ---------------------------------------------------------------------------
// K2: fused x1 = in@w1 + b1 (stored transposed [B,H,T]); q = in@w2 + ms@w3.
// ---------------------------------------------------------------------------
__global__ __launch_bounds__(256) void k_gemm1(
    const float* __restrict__ in,
    const float* __restrict__ w1, const float* __restrict__ w1b,
    const float* __restrict__ w2, const float* __restrict__ w3)
{
    __shared__ float s_in[HH][36];
    __shared__ float s_ms[HH][36];
    int tid = threadIdx.x;
    int row0 = blockIdx.x * 32;

    for (int idx = tid; idx < 32 * HH; idx += 256) {
        int r = idx >> 7, h = idx & 127;
        s_in[h][r] = in[(row0 + r) * HH + h];
        s_ms[h][r] = g_ms[(row0 + r) * HH + h];
    }
    __syncthreads();

    int c = tid & 127;
    int rh = tid >> 7;           // 0/1 -> rows rh*16 .. rh*16+15
    float a1[16], a2[16];
#pragma unroll
    for (int r = 0; r < 16; r++) { a1[r] = 0.0f; a2[r] = 0.0f; }

#pragma unroll 4
    for (int h = 0; h < HH; h++) {
        float w1v = w1[h * HH + c];
        float w2v = w2[h * HH + c];
        float w3v = w3[h * HH + c];
        const float4* pi = (const float4*)&s_in[h][rh * 16];
        const float4* pm = (const float4*)&s_ms[h][rh * 16];
#pragma unroll
        for (int k = 0; k < 4; k++) {
            float4 vi = pi[k];
            float4 vm = pm[k];
            a1[4*k+0] = fmaf(vi.x, w1v, a1[4*k+0]);
            a1[4*k+1] = fmaf(vi.y, w1v, a1[4*k+1]);
            a1[4*k+2] = fmaf(vi.z, w1v, a1[4*k+2]);
            a1[4*k+3] = fmaf(vi.w, w1v, a1[4*k+3]);
            a2[4*k+0] = fmaf(vi.x, w2v, fmaf(vm.x, w3v, a2[4*k+0]));
            a2[4*k+1] = fmaf(vi.y, w2v, fmaf(vm.y, w3v, a2[4*k+1]));
            a2[4*k+2] = fmaf(vi.z, w2v, fmaf(vm.z, w3v, a2[4*k+2]));
            a2[4*k+3] = fmaf(vi.w, w2v, fmaf(vm.w, w3v, a2[4*k+3]));
        }
    }
    float bias = w1b[c];
#pragma unroll
    for (int r = 0; r < 16; r++) {
        int grow = row0 + rh * 16 + r;
        int t = grow >> 6;        // row = t*B + b
        int b = grow & 63;
        g_x1T[(b * HH + c) * TT + t] = a1[r] + bias;
        g_q[grow * HH + c] = a2[r];
    }
}

// ---------------------------------------------------------------------------
// K3: scores + m_a, i-tiled. One block per (i-tile of 16, b), 256 threads.
// sigmoid via tanh.approx: sig(x) = 0.5 + 0.5*tanh(x/2).
// ---------------------------------------------------------------------------
__global__ __launch_bounds__(256) void k_scores(
    const float* __restrict__ in, const float* __restrict__ w0)
{
    int i0 = blockIdx.x * 16;
    int b  = blockIdx.y;
    __shared__ float qh[16][HH];      // 0.5 * q[i,b,:]
    __shared__ float w0s[HH];
    __shared__ float ssh[16][132];    // scores, padded
    __shared__ float w0sum_sh;

    int tid = threadIdx.x;
    for (int idx = tid; idx < 16 * HH; idx += 256) {
        int il = idx >> 7, h = idx & 127;
        qh[il][h] = g_q[((i0 + il) * BB + b) * HH + h] * 0.5f;
    }
    if (tid < 128) w0s[tid] = w0[tid];
    __syncthreads();
    if (tid < 32) {
        float s = w0s[tid] + w0s[tid+32] + w0s[tid+64] + w0s[tid+96];
#pragma unroll
        for (int off = 16; off; off >>= 1) s += __shfl_xor_sync(0xFFFFFFFFu, s, off);
        if (tid == 0) w0sum_sh = s;
    }
    __syncthreads();
    float w0sum = w0sum_sh;

    // ---- phase 1: scores ----
    int j  = tid & 127;
    int ih = (tid >> 7) * 8;          // 8 i's per thread
    float acc[8];
#pragma unroll
    for (int k = 0; k < 8; k++) acc[k] = 0.0f;

    if (j < i0 + 16) {                // causally relevant j only
        const float* xp = g_x1T + b * (HH * TT) + j;
#pragma unroll 2
        for (int h = 0; h < HH; h++) {
            float x1v = xp[h * TT] * 0.5f;
            float wv = w0s[h];
#pragma unroll
            for (int k = 0; k < 8; k++) {
                float t = ftanh(x1v + qh[ih + k][h]);
                acc[k] = fmaf(wv, t, acc[k]);
            }
        }
    }
#pragma unroll
    for (int k = 0; k < 8; k++) {
        int ig = i0 + ih + k;
        ssh[ih + k][j] = (j <= ig) ? 0.5f * (acc[k] + w0sum) : 0.0f;
    }
    __syncthreads();

    // ---- phase 2: m_a ----
    int h   = tid & 127;
    int ih2 = (tid >> 7) * 8;
    float m[8];
#pragma unroll
    for (int k = 0; k < 8; k++) m[k] = 0.0f;

    const float* ip = in + b * HH + h;
    int jmax = i0 + 16;
    for (int jj = 0; jj < jmax; jj += 4) {
        float v0 = ip[(jj + 0) * (BB*HH)];
        float v1 = ip[(jj + 1) * (BB*HH)];
        float v2 = ip[(jj + 2) * (BB*HH)];
        float v3 = ip[(jj + 3) * (BB*HH)];
#pragma unroll
        for (int k = 0; k < 8; k++) {
            float4 s4 = *(const float4*)&ssh[ih2 + k][jj];
            m[k] = fmaf(s4.x, v0, fmaf(s4.y, v1, fmaf(s4.z, v2, fmaf(s4.w, v3, m[k]))));
        }
    }
#pragma unroll
    for (int k = 0; k < 8; k++)
        g_ma[((i0 + ih2 + k) * BB + b) * HH + h] = m[k];
}

// ---------------------------------------------------------------------------
// K4: predict heads. 16 rows/block, grid (512, 2): blockIdx.y = pass (c / v).
// Pass v writes the RAW sigmoid; k_mul multiplies by pc afterwards.
// 2-D register tile 4x4; weight LDGs batched via unroll 8.
// ---------------------------------------------------------------------------
__global__ __launch_bounds__(256) void k_predict(
    const float* __restrict__ in,
    const float* __restrict__ c0a, const float* __restrict__ c0ab,
    const float* __restrict__ c0b, const float* __restrict__ c0bb,
    const float* __restrict__ c1a, const float* __restrict__ c1ab,
    const float* __restrict__ c1b, const float* __restrict__ c1bb,
    const float* __restrict__ v0a, const float* __restrict__ v0ab,
    const float* __restrict__ v0b, const float* __restrict__ v0bb,
    const float* __restrict__ v1a, const float* __restrict__ v1ab,
    const float* __restrict__ v1b, const float* __restrict__ v1bb,
    float* __restrict__ out)
{
    __shared__ float sbuf[2][HH][20];   // inputs, then layer0 acts (reused)
    __shared__ float sl1[2][16][68];    // layer1 outputs

    const int ROWS = 16;
    int tid    = threadIdx.x;
    int row0   = blockIdx.x * ROWS;
    int pass   = blockIdx.y;
    int branch = tid >> 7;              // 0: a-side (m_a), 1: b-side (inputs)
    int t7     = tid & 127;

    const float *k0, *k0bias, *k1, *k1bias;
    if (pass == 0) { k0 = branch ? c0b : c0a; k0bias = branch ? c0bb : c0ab;
                     k1 = branch ? c1b : c1a; k1bias = branch ? c1bb : c1ab; }
    else           { k0 = branch ? v0b : v0a; k0bias = branch ? v0bb : v0ab;
                     k1 = branch ? v1b : v1a; k1bias = branch ? v1bb : v1ab; }

    // ---- load inputs transposed [h][row] ----
    for (int idx = tid; idx < ROWS * HH; idx += 256) {
        int h = idx & 127, r = idx >> 7;
        sbuf[0][h][r] = g_ma[(row0 + r) * HH + h];
        sbuf[1][h][r] = in[(row0 + r) * HH + h];
    }
    __syncthreads();

    // ---- layer 0: [16,128] x [128,128] per branch, 4 cols x 4 rows/thread --
    int cg = t7 & 31;               // cols cg*4 .. cg*4+3   (== lane)
    int rg = t7 >> 5;               // rows rg*4 .. rg*4+3
    float a0[16];
#pragma unroll
    for (int x = 0; x < 16; x++) a0[x] = 0.0f;

#pragma unroll 8
    for (int h = 0; h < HH; h++) {
        float4 w4 = *(const float4*)&k0[h * EE0 + cg * 4];
        float4 v4 = *(const float4*)&sbuf[branch][h][rg * 4];
        float wv[4] = {w4.x, w4.y, w4.z, w4.w};
        float rv[4] = {v4.x, v4.y, v4.z, v4.w};
#pragma unroll
        for (int cc = 0; cc < 4; cc++)
#pragma unroll
            for (int rr = 0; rr < 4; rr++)
                a0[cc * 4 + rr] = fmaf(wv[cc], rv[rr], a0[cc * 4 + rr]);
    }
    float4 b0v = *(const float4*)&k0bias[cg * 4];
    float b0[4] = {b0v.x, b0v.y, b0v.z, b0v.w};
    __syncthreads();   // all reads of sbuf inputs done
#pragma unroll
    for (int cc = 0; cc < 4; cc++) {
        float4 t0 = make_float4(leakyf_(a0[cc * 4 + 0] + b0[cc]),
                                leakyf_(a0[cc * 4 + 1] + b0[cc]),
                                leakyf_(a0[cc * 4 + 2] + b0[cc]),
                                leakyf_(a0[cc * 4 + 3] + b0[cc]));
        *(float4*)&sbuf[branch][cg * 4 + cc][rg * 4] = t0;
    }
    __syncthreads();

    // ---- layer 1: [16,128] x [128,64] per branch, 4 cols x 2 rows/thread --
    int cg2 = t7 & 15;              // cols cg2*4 of 64
    int rg2 = t7 >> 4;              // rows rg2*2 of 16
    float a1[8];
#pragma unroll
    for (int x = 0; x < 8; x++) a1[x] = 0.0f;

#pragma unroll 8
    for (int h = 0; h < EE0; h++) {
        float4 w4 = *(const float4*)&k1[h * EE1 + cg2 * 4];
        float2 v2 = *(const float2*)&sbuf[branch][h][rg2 * 2];
        float wv[4] = {w4.x, w4.y, w4.z, w4.w};
#pragma unroll
        for (int cc = 0; cc < 4; cc++) {
            a1[cc * 2 + 0] = fmaf(wv[cc], v2.x, a1[cc * 2 + 0]);
            a1[cc * 2 + 1] = fmaf(wv[cc], v2.y, a1[cc * 2 + 1]);
        }
    }
    float4 b1v = *(const float4*)&k1bias[cg2 * 4];
    float b1[4] = {b1v.x, b1v.y, b1v.z, b1v.w};

#pragma unroll
    for (int rr = 0; rr < 2; rr++) {
        float4 v = make_float4(leakyf_(a1[0 * 2 + rr] + b1[0]),
                               leakyf_(a1[1 * 2 + rr] + b1[1]),
                               leakyf_(a1[2 * 2 + rr] + b1[2]),
                               leakyf_(a1[3 * 2 + rr] + b1[3]));
        *(float4*)&sl1[branch][rg2 * 2 + rr][cg2 * 4] = v;
    }
    __syncthreads();

    // ---- product + reduce + sigmoid ----
    int row = tid >> 4;             // 0..15
    int lg  = tid & 15;             // 16 lanes per row, 4 elems each
    float4 a4 = *(const float4*)&sl1[0][row][lg * 4];
    float4 b4 = *(const float4*)&sl1[1][row][lg * 4];
    float p = a4.x*b4.x + a4.y*b4.y + a4.z*b4.z + a4.w*b4.w;
    p += __shfl_xor_sync(0xFFFFFFFFu, p, 8);
    p += __shfl_xor_sync(0xFFFFFFFFu, p, 4);
    p += __shfl_xor_sync(0xFFFFFFFFu, p, 2);
    p += __shfl_xor_sync(0xFFFFFFFFu, p, 1);
    if (lg == 0)
        out[pass * TB + row0 + row] = sigmoidf_(p);
}

// ---------------------------------------------------------------------------
// K5: out[TB+i] *= out[i]  (pv = raw_pv * pc)
// ---------------------------------------------------------------------------
__global__ __launch_bounds__(256) void k_mul(float* __restrict__ out) {
    int i = blockIdx.x * 256 + threadIdx.x;
    out[TB + i] *= out[i];
}

// ---------------------------------------------------------------------------
extern "C" void kernel_launch(void* const* d_in, const int* in_sizes, int n_in,
                              void* d_out, int out_size)
{
    (void)in_sizes; (void)n_in; (void)out_size;
    const float* in_  = (const float*)d_in[0];
    const float* w1k  = (const float*)d_in[1];
    const float* w1b  = (const float*)d_in[2];
    const float* w2k  = (const float*)d_in[3];
    const float* w3k  = (const float*)d_in[4];
    const float* w0k  = (const float*)d_in[5];
    const float* pc0a = (const float*)d_in[6];
    const float* pc0ab= (const float*)d_in[7];
    const float* pc0b = (const float*)d_in[8];
    const float* pc0bb= (const float*)d_in[9];
    const float* pc1a = (const float*)d_in[10];
    const float* pc1ab= (const float*)d_in[11];
    const float* pc1b = (const float*)d_in[12];
    const float* pc1bb= (const float*)d_in[13];
    const float* pv0a = (const float*)d_in[14];
    const float* pv0ab= (const float*)d_in[15];
    const float* pv0b = (const float*)d_in[16];
    const float* pv0bb= (const float*)d_in[17];
    const float* pv1a = (const float*)d_in[18];
    const float* pv1ab= (const float*)d_in[19];
    const float* pv1b = (const float*)d_in[20];
    const float* pv1bb= (const float*)d_in[21];
    float* out = (float*)d_out;

    k_cumsum<<<BB*HH/128, 128>>>(in_);
    k_gemm1<<<TB/32, 256>>>(in_, w1k, w1b, w2k, w3k);
    k_scores<<<dim3(TT/16, BB), 256>>>(in_, w0k);
    k_predict<<<dim3(TB/16, 2), 256>>>(in_,
        pc0a, pc0ab, pc0b, pc0bb, pc1a, pc1ab, pc1b, pc1bb,
        pv0a, pv0ab, pv0b, pv0bb, pv1a, pv1ab, pv1b, pv1bb,
        out);
    k_mul<<<TB/256, 256>>>(out);
}

// round 4
// speedup vs baseline: 1.0410x; 1.0410x over previous
#include <cuda_runtime.h>

#define TT 128
#define BB 64
#define HH 128
#define EE0 128
#define EE1 64
#define TB (TT*BB)
#define LOG2E 1.4426950408889634f

// Scratch (device globals: no allocation allowed in kernel_launch)
__device__ float g_ms[TT*BB*HH];    // running mean  [T,B,H]
__device__ float g_x1T[BB*HH*TT];   // x1 transposed [B,H,T]
__device__ float g_q[TT*BB*HH];     // x2 + wms      [T,B,H]
__device__ float g_ma[TT*BB*HH];    // m_a           [T,B,H]

__device__ __forceinline__ float fex2(float x){ float r; asm("ex2.approx.f32 %0, %1;" : "=f"(r) : "f"(x)); return r; }
__device__ __forceinline__ float frcp(float x){ float r; asm("rcp.approx.f32 %0, %1;" : "=f"(r) : "f"(x)); return r; }
__device__ __forceinline__ float ftanh(float x){ float r; asm("tanh.approx.f32 %0, %1;" : "=f"(r) : "f"(x)); return r; }
__device__ __forceinline__ float sigmoidf_(float x){ return frcp(1.0f + fex2(x * -LOG2E)); }
__device__ __forceinline__ float leakyf_(float x){ return x > 0.0f ? x : 0.3f * x; }

// ---------------------------------------------------------------------------
// K1: running mean over time prefix. 8192 threads = (b,h); 128 blocks x 64.
// ---------------------------------------------------------------------------
__global__ __launch_bounds__(64) void k_cumsum(const float* __restrict__ in) {
    int idx = blockIdx.x * 64 + threadIdx.x;   // b*H + h
    float acc = 0.0f;
#pragma unroll 4
    for (int t = 0; t < TT; t++) {
        acc += in[t * (BB*HH) + idx];
        g_ms[t * (BB*HH) + idx] = acc / (float)(t + 1);
    }
}

// ---------------------------------------------------------------------------
// K2: fused x1 = in@w1 + b1 (stored transposed [B,H,T]); q = in@w2 + ms@w3.
// Weight loads explicitly front-batched in chunks of 4 h (12 LDG in flight).
// ---------------------------------------------------------------------------
__global__ __launch_bounds__(256) void k_gemm1(
    const float* __restrict__ in,
    const float* __restrict__ w1, const float* __restrict__ w1b,
    const float* __restrict__ w2, const float* __restrict__ w3)
{
    __shared__ float s_in[HH][36];
    __shared__ float s_ms[HH][36];
    int tid = threadIdx.x;
    int row0 = blockIdx.x * 32;

    for (int idx = tid; idx < 32 * HH; idx += 256) {
        int r = idx >> 7, h = idx & 127;
        s_in[h][r] = in[(row0 + r) * HH + h];
        s_ms[h][r] = g_ms[(row0 + r) * HH + h];
    }
    __syncthreads();

    int c = tid & 127;
    int rh = tid >> 7;           // 0/1 -> rows rh*16 .. rh*16+15
    float a1[16], a2[16];
#pragma unroll
    for (int r = 0; r < 16; r++) { a1[r] = 0.0f; a2[r] = 0.0f; }

    for (int hb = 0; hb < HH; hb += 4) {
        float w1v[4], w2v[4], w3v[4];
#pragma unroll
        for (int k = 0; k < 4; k++) {
            w1v[k] = w1[(hb + k) * HH + c];
            w2v[k] = w2[(hb + k) * HH + c];
            w3v[k] = w3[(hb + k) * HH + c];
        }
#pragma unroll
        for (int k = 0; k < 4; k++) {
            const float4* pi = (const float4*)&s_in[hb + k][rh * 16];
            const float4* pm = (const float4*)&s_ms[hb + k][rh * 16];
#pragma unroll
            for (int q4 = 0; q4 < 4; q4++) {
                float4 vi = pi[q4];
                float4 vm = pm[q4];
                a1[4*q4+0] = fmaf(vi.x, w1v[k], a1[4*q4+0]);
                a1[4*q4+1] = fmaf(vi.y, w1v[k], a1[4*q4+1]);
                a1[4*q4+2] = fmaf(vi.z, w1v[k], a1[4*q4+2]);
                a1[4*q4+3] = fmaf(vi.w, w1v[k], a1[4*q4+3]);
                a2[4*q4+0] = fmaf(vi.x, w2v[k], fmaf(vm.x, w3v[k], a2[4*q4+0]));
                a2[4*q4+1] = fmaf(vi.y, w2v[k], fmaf(vm.y, w3v[k], a2[4*q4+1]));
                a2[4*q4+2] = fmaf(vi.z, w2v[k], fmaf(vm.z, w3v[k], a2[4*q4+2]));
                a2[4*q4+3] = fmaf(vi.w, w2v[k], fmaf(vm.w, w3v[k], a2[4*q4+3]));
            }
        }
    }
    float bias = w1b[c];
#pragma unroll
    for (int r = 0; r < 16; r++) {
        int grow = row0 + rh * 16 + r;
        int t = grow >> 6;        // row = t*B + b
        int b = grow & 63;
        g_x1T[(b * HH + c) * TT + t] = a1[r] + bias;
        g_q[grow * HH + c] = a2[r];
    }
}

// ---------------------------------------------------------------------------
// K3: scores + m_a, i-tiled. One block per (i-tile of 16, b), 256 threads.
// sigmoid via tanh.approx: sig(x) = 0.5 + 0.5*tanh(x/2).
// x1T loads front-batched in chunks of 4.
// ---------------------------------------------------------------------------
__global__ __launch_bounds__(256) void k_scores(
    const float* __restrict__ in, const float* __restrict__ w0)
{
    int i0 = blockIdx.x * 16;
    int b  = blockIdx.y;
    __shared__ float qh[16][HH];      // 0.5 * q[i,b,:]
    __shared__ float w0s[HH];
    __shared__ float ssh[16][132];    // scores, padded
    __shared__ float w0sum_sh;

    int tid = threadIdx.x;
    for (int idx = tid; idx < 16 * HH; idx += 256) {
        int il = idx >> 7, h = idx & 127;
        qh[il][h] = g_q[((i0 + il) * BB + b) * HH + h] * 0.5f;
    }
    if (tid < 128) w0s[tid] = w0[tid];
    __syncthreads();
    if (tid < 32) {
        float s = w0s[tid] + w0s[tid+32] + w0s[tid+64] + w0s[tid+96];
#pragma unroll
        for (int off = 16; off; off >>= 1) s += __shfl_xor_sync(0xFFFFFFFFu, s, off);
        if (tid == 0) w0sum_sh = s;
    }
    __syncthreads();
    float w0sum = w0sum_sh;

    // ---- phase 1: scores ----
    int j  = tid & 127;
    int ih = (tid >> 7) * 8;          // 8 i's per thread
    float acc[8];
#pragma unroll
    for (int k = 0; k < 8; k++) acc[k] = 0.0f;

    if (j < i0 + 16) {                // causally relevant j only
        const float* xp = g_x1T + b * (HH * TT) + j;
        for (int hb = 0; hb < HH; hb += 4) {
            float x1v[4];
#pragma unroll
            for (int k = 0; k < 4; k++) x1v[k] = xp[(hb + k) * TT];
#pragma unroll
            for (int k = 0; k < 4; k++) {
                float xv = x1v[k] * 0.5f;
                float wv = w0s[hb + k];
#pragma unroll
                for (int kk = 0; kk < 8; kk++) {
                    float t = ftanh(xv + qh[ih + kk][hb + k]);
                    acc[kk] = fmaf(wv, t, acc[kk]);
                }
            }
        }
    }
#pragma unroll
    for (int k = 0; k < 8; k++) {
        int ig = i0 + ih + k;
        ssh[ih + k][j] = (j <= ig) ? 0.5f * (acc[k] + w0sum) : 0.0f;
    }
    __syncthreads();

    // ---- phase 2: m_a ----
    int h   = tid & 127;
    int ih2 = (tid >> 7) * 8;
    float m[8];
#pragma unroll
    for (int k = 0; k < 8; k++) m[k] = 0.0f;

    const float* ip = in + b * HH + h;
    int jmax = i0 + 16;
    for (int jj = 0; jj < jmax; jj += 4) {
        float v0 = ip[(jj + 0) * (BB*HH)];
        float v1 = ip[(jj + 1) * (BB*HH)];
        float v2 = ip[(jj + 2) * (BB*HH)];
        float v3 = ip[(jj + 3) * (BB*HH)];
#pragma unroll
        for (int k = 0; k < 8; k++) {
            float4 s4 = *(const float4*)&ssh[ih2 + k][jj];
            m[k] = fmaf(s4.x, v0, fmaf(s4.y, v1, fmaf(s4.z, v2, fmaf(s4.w, v3, m[k]))));
        }
    }
#pragma unroll
    for (int k = 0; k < 8; k++)
        g_ma[((i0 + ih2 + k) * BB + b) * HH + h] = m[k];
}

// ---------------------------------------------------------------------------
// K4: predict heads. 32 rows/block, grid (256, 2): blockIdx.y = pass (c / v).
// Pass v writes the RAW sigmoid; k_mul multiplies by pc afterwards.
// Weight LDGs front-batched by explicit chunk-4 register arrays.
// Layer0: 4 cols x 8 rows/thread. Layer1: 4 cols x 4 rows/thread.
// ---------------------------------------------------------------------------
__global__ __launch_bounds__(256) void k_predict(
    const float* __restrict__ in,
    const float* __restrict__ c0a, const float* __restrict__ c0ab,
    const float* __restrict__ c0b, const float* __restrict__ c0bb,
    const float* __restrict__ c1a, const float* __restrict__ c1ab,
    const float* __restrict__ c1b, const float* __restrict__ c1bb,
    const float* __restrict__ v0a, const float* __restrict__ v0ab,
    const float* __restrict__ v0b, const float* __restrict__ v0bb,
    const float* __restrict__ v1a, const float* __restrict__ v1ab,
    const float* __restrict__ v1b, const float* __restrict__ v1bb,
    float* __restrict__ out)
{
    __shared__ float sbuf[2][HH][36];   // inputs -> layer0 acts -> layer1 outs
    const int ROWS = 32;
    int tid    = threadIdx.x;
    int row0   = blockIdx.x * ROWS;
    int pass   = blockIdx.y;
    int branch = tid >> 7;              // 0: a-side (m_a), 1: b-side (inputs)
    int t7     = tid & 127;

    const float *k0, *k0bias, *k1, *k1bias;
    if (pass == 0) { k0 = branch ? c0b : c0a; k0bias = branch ? c0bb : c0ab;
                     k1 = branch ? c1b : c1a; k1bias = branch ? c1bb : c1ab; }
    else           { k0 = branch ? v0b : v0a; k0bias = branch ? v0bb : v0ab;
                     k1 = branch ? v1b : v1a; k1bias = branch ? v1bb : v1ab; }

    // ---- load inputs transposed [h][row] ----
    for (int idx = tid; idx < ROWS * HH; idx += 256) {
        int h = idx & 127, r = idx >> 7;
        sbuf[0][h][r] = g_ma[(row0 + r) * HH + h];
        sbuf[1][h][r] = in[(row0 + r) * HH + h];
    }
    __syncthreads();

    // ---- layer 0: [32,128] x [128,128] per branch, 4 cols x 8 rows/thread --
    int cg = t7 & 31;               // cols cg*4 .. cg*4+3
    int rg = t7 >> 5;               // rows rg*8 .. rg*8+7
    float a0[32];
#pragma unroll
    for (int x = 0; x < 32; x++) a0[x] = 0.0f;

    for (int hb = 0; hb < HH; hb += 4) {
        float4 w[4];
#pragma unroll
        for (int k = 0; k < 4; k++)
            w[k] = *(const float4*)&k0[(hb + k) * EE0 + cg * 4];
#pragma unroll
        for (int k = 0; k < 4; k++) {
            float4 va = *(const float4*)&sbuf[branch][hb + k][rg * 8];
            float4 vb = *(const float4*)&sbuf[branch][hb + k][rg * 8 + 4];
            float wv[4] = {w[k].x, w[k].y, w[k].z, w[k].w};
            float rv[8] = {va.x, va.y, va.z, va.w, vb.x, vb.y, vb.z, vb.w};
#pragma unroll
            for (int cc = 0; cc < 4; cc++)
#pragma unroll
                for (int rr = 0; rr < 8; rr++)
                    a0[cc * 8 + rr] = fmaf(wv[cc], rv[rr], a0[cc * 8 + rr]);
        }
    }
    float4 b0v = *(const float4*)&k0bias[cg * 4];
    float b0[4] = {b0v.x, b0v.y, b0v.z, b0v.w};
    __syncthreads();   // all reads of sbuf inputs done
#pragma unroll
    for (int cc = 0; cc < 4; cc++) {
        float t0[8];
#pragma unroll
        for (int rr = 0; rr < 8; rr++) t0[rr] = leakyf_(a0[cc * 8 + rr] + b0[cc]);
        float* dst = &sbuf[branch][cg * 4 + cc][rg * 8];
        *(float4*)(dst)     = make_float4(t0[0], t0[1], t0[2], t0[3]);
        *(float4*)(dst + 4) = make_float4(t0[4], t0[5], t0[6], t0[7]);
    }
    __syncthreads();

    // ---- layer 1: [32,128] x [128,64] per branch, 4 cols x 4 rows/thread --
    int cg2 = t7 & 15;              // cols cg2*4 of 64
    int rg2 = t7 >> 4;              // rows rg2*4 of 32
    float a1[16];
#pragma unroll
    for (int x = 0; x < 16; x++) a1[x] = 0.0f;

    for (int hb = 0; hb < EE0; hb += 4) {
        float4 w[4];
#pragma unroll
        for (int k = 0; k < 4; k++)
            w[k] = *(const float4*)&k1[(hb + k) * EE1 + cg2 * 4];
#pragma unroll
        for (int k = 0; k < 4; k++) {
            float4 v4 = *(const float4*)&sbuf[branch][hb + k][rg2 * 4];
            float wv[4] = {w[k].x, w[k].y, w[k].z, w[k].w};
            float rv[4] = {v4.x, v4.y, v4.z, v4.w};
#pragma unroll
            for (int cc = 0; cc < 4; cc++)
#pragma unroll
                for (int rr = 0; rr < 4; rr++)
                    a1[cc * 4 + rr] = fmaf(wv[cc], rv[rr], a1[cc * 4 + rr]);
        }
    }
    float4 b1v = *(const float4*)&k1bias[cg2 * 4];
    float b1[4] = {b1v.x, b1v.y, b1v.z, b1v.w};
    __syncthreads();   // all reads of layer0 acts done

    // write activated layer1 outputs into reused sbuf: [branch*32+row][68]
    float* sl1 = &sbuf[0][0][0];
#pragma unroll
    for (int rr = 0; rr < 4; rr++) {
        int row = rg2 * 4 + rr;
        float4 v = make_float4(leakyf_(a1[0 * 4 + rr] + b1[0]),
                               leakyf_(a1[1 * 4 + rr] + b1[1]),
                               leakyf_(a1[2 * 4 + rr] + b1[2]),
                               leakyf_(a1[3 * 4 + rr] + b1[3]));
        *(float4*)&sl1[(branch * 32 + row) * 68 + cg2 * 4] = v;
    }
    __syncthreads();

    // ---- product + reduce + sigmoid ----
    int row = tid >> 3;             // 0..31
    int lg  = tid & 7;              // 8 lanes per row, 8 elems each
    const float* pa = &sl1[(0 * 32 + row) * 68 + lg * 8];
    const float* pb = &sl1[(1 * 32 + row) * 68 + lg * 8];
    float4 a4 = *(const float4*)pa, a5 = *(const float4*)(pa + 4);
    float4 b4 = *(const float4*)pb, b5 = *(const float4*)(pb + 4);
    float p = a4.x*b4.x + a4.y*b4.y + a4.z*b4.z + a4.w*b4.w
            + a5.x*b5.x + a5.y*b5.y + a5.z*b5.z + a5.w*b5.w;
    p += __shfl_xor_sync(0xFFFFFFFFu, p, 4);
    p += __shfl_xor_sync(0xFFFFFFFFu, p, 2);
    p += __shfl_xor_sync(0xFFFFFFFFu, p, 1);
    if (lg == 0)
        out[pass * TB + row0 + row] = sigmoidf_(p);
}

// ---------------------------------------------------------------------------
// K5: out[TB+i] *= out[i]  (pv = raw_pv * pc)
// ---------------------------------------------------------------------------
__global__ __launch_bounds__(256) void k_mul(float* __restrict__ out) {
    int i = blockIdx.x * 256 + threadIdx.x;
    out[TB + i] *= out[i];
}

// ---------------------------------------------------------------------------
extern "C" void kernel_launch(void* const* d_in, const int* in_sizes, int n_in,
                              void* d_out, int out_size)
{
    (void)in_sizes; (void)n_in; (void)out_size;
    const float* in_  = (const float*)d_in[0];
    const float* w1k  = (const float*)d_in[1];
    const float* w1b  = (const float*)d_in[2];
    const float* w2k  = (const float*)d_in[3];
    const float* w3k  = (const float*)d_in[4];
    const float* w0k  = (const float*)d_in[5];
    const float* pc0a = (const float*)d_in[6];
    const float* pc0ab= (const float*)d_in[7];
    const float* pc0b = (const float*)d_in[8];
    const float* pc0bb= (const float*)d_in[9];
    const float* pc1a = (const float*)d_in[10];
    const float* pc1ab= (const float*)d_in[11];
    const float* pc1b = (const float*)d_in[12];
    const float* pc1bb= (const float*)d_in[13];
    const float* pv0a = (const float*)d_in[14];
    const float* pv0ab= (const float*)d_in[15];
    const float* pv0b = (const float*)d_in[16];
    const float* pv0bb= (const float*)d_in[17];
    const float* pv1a = (const float*)d_in[18];
    const float* pv1ab= (const float*)d_in[19];
    const float* pv1b = (const float*)d_in[20];
    const float* pv1bb= (const float*)d_in[21];
    float* out = (float*)d_out;

    k_cumsum<<<BB*HH/64, 64>>>(in_);
    k_gemm1<<<TB/32, 256>>>(in_, w1k, w1b, w2k, w3k);
    k_scores<<<dim3(TT/16, BB), 256>>>(in_, w0k);
    k_predict<<<dim3(TB/32, 2), 256>>>(in_,
        pc0a, pc0ab, pc0b, pc0bb, pc1a, pc1ab, pc1b, pc1bb,
        pv0a, pv0ab, pv0b, pv0bb, pv1a, pv1ab, pv1b, pv1bb,
        out);
    k_mul<<<TB/256, 256>>>(out);
}

// round 5
// speedup vs baseline: 1.0986x; 1.0554x over previous
#include <cuda_runtime.h>

#define TT 128
#define BB 64
#define HH 128
#define EE0 128
#define EE1 64
#define TB (TT*BB)
#define LOG2E 1.4426950408889634f

// Scratch (device globals: no allocation allowed in kernel_launch)
__device__ float g_ms[TT*BB*HH];    // running mean  [T,B,H]
__device__ float g_x1T[BB*HH*TT];   // x1 transposed [B,H,T]
__device__ float g_q[TT*BB*HH];     // x2 + wms      [T,B,H]
__device__ float g_ma[TT*BB*HH];    // m_a           [T,B,H]

__device__ __forceinline__ float fex2(float x){ float r; asm("ex2.approx.f32 %0, %1;" : "=f"(r) : "f"(x)); return r; }
__device__ __forceinline__ float frcp(float x){ float r; asm("rcp.approx.f32 %0, %1;" : "=f"(r) : "f"(x)); return r; }
__device__ __forceinline__ float ftanh(float x){ float r; asm("tanh.approx.f32 %0, %1;" : "=f"(r) : "f"(x)); return r; }
__device__ __forceinline__ float sigmoidf_(float x){ return frcp(1.0f + fex2(x * -LOG2E)); }
__device__ __forceinline__ float leakyf_(float x){ return x > 0.0f ? x : 0.3f * x; }

// ---------------------------------------------------------------------------
// K1: running mean over time prefix (exact R2 version — measured good).
// ---------------------------------------------------------------------------
__global__ __launch_bounds__(128) void k_cumsum(const float* __restrict__ in) {
    int idx = blockIdx.x * 128 + threadIdx.x;   // b*H + h
    float acc = 0.0f;
#pragma unroll 4
    for (int t = 0; t < TT; t++) {
        acc += in[t * (BB*HH) + idx];
        g_ms[t * (BB*HH) + idx] = acc / (float)(t + 1);
    }
}

// ---------------------------------------------------------------------------
// K2: fused x1 = in@w1 + b1 (stored transposed [B,H,T]); q = in@w2 + ms@w3.
// Exact R2 version (no weight prefetch — 32 accs leave no register headroom).
// ---------------------------------------------------------------------------
__global__ __launch_bounds__(256) void k_gemm1(
    const float* __restrict__ in,
    const float* __restrict__ w1, const float* __restrict__ w1b,
    const float* __restrict__ w2, const float* __restrict__ w3)
{
    __shared__ float s_in[HH][36];
    __shared__ float s_ms[HH][36];
    int tid = threadIdx.x;
    int row0 = blockIdx.x * 32;

    for (int idx = tid; idx < 32 * HH; idx += 256) {
        int r = idx >> 7, h = idx & 127;
        s_in[h][r] = in[(row0 + r) * HH + h];
        s_ms[h][r] = g_ms[(row0 + r) * HH + h];
    }
    __syncthreads();

    int c = tid & 127;
    int rh = tid >> 7;           // 0/1 -> rows rh*16 .. rh*16+15
    float a1[16], a2[16];
#pragma unroll
    for (int r = 0; r < 16; r++) { a1[r] = 0.0f; a2[r] = 0.0f; }

    for (int h = 0; h < HH; h++) {
        float w1v = w1[h * HH + c];
        float w2v = w2[h * HH + c];
        float w3v = w3[h * HH + c];
        const float4* pi = (const float4*)&s_in[h][rh * 16];
        const float4* pm = (const float4*)&s_ms[h][rh * 16];
#pragma unroll
        for (int k = 0; k < 4; k++) {
            float4 vi = pi[k];
            float4 vm = pm[k];
            a1[4*k+0] = fmaf(vi.x, w1v, a1[4*k+0]);
            a1[4*k+1] = fmaf(vi.y, w1v, a1[4*k+1]);
            a1[4*k+2] = fmaf(vi.z, w1v, a1[4*k+2]);
            a1[4*k+3] = fmaf(vi.w, w1v, a1[4*k+3]);
            a2[4*k+0] = fmaf(vi.x, w2v, fmaf(vm.x, w3v, a2[4*k+0]));
            a2[4*k+1] = fmaf(vi.y, w2v, fmaf(vm.y, w3v, a2[4*k+1]));
            a2[4*k+2] = fmaf(vi.z, w2v, fmaf(vm.z, w3v, a2[4*k+2]));
            a2[4*k+3] = fmaf(vi.w, w2v, fmaf(vm.w, w3v, a2[4*k+3]));
        }
    }
    float bias = w1b[c];
#pragma unroll
    for (int r = 0; r < 16; r++) {
        int grow = row0 + rh * 16 + r;
        int t = grow >> 6;        // row = t*B + b
        int b = grow & 63;
        g_x1T[(b * HH + c) * TT + t] = a1[r] + bias;
        g_q[grow * HH + c] = a2[r];
    }
}

// ---------------------------------------------------------------------------
// K3: scores + m_a, i-tiled (exact R2 version — measured good).
// ---------------------------------------------------------------------------
__global__ __launch_bounds__(256) void k_scores(
    const float* __restrict__ in, const float* __restrict__ w0)
{
    int i0 = blockIdx.x * 16;
    int b  = blockIdx.y;
    __shared__ float qh[16][HH];      // 0.5 * q[i,b,:]
    __shared__ float w0s[HH];
    __shared__ float ssh[16][132];    // scores, padded
    __shared__ float w0sum_sh;

    int tid = threadIdx.x;
    for (int idx = tid; idx < 16 * HH; idx += 256) {
        int il = idx >> 7, h = idx & 127;
        qh[il][h] = g_q[((i0 + il) * BB + b) * HH + h] * 0.5f;
    }
    if (tid < 128) w0s[tid] = w0[tid];
    __syncthreads();
    if (tid < 32) {
        float s = w0s[tid] + w0s[tid+32] + w0s[tid+64] + w0s[tid+96];
#pragma unroll
        for (int off = 16; off; off >>= 1) s += __shfl_xor_sync(0xFFFFFFFFu, s, off);
        if (tid == 0) w0sum_sh = s;
    }
    __syncthreads();
    float w0sum = w0sum_sh;

    // ---- phase 1: scores ----
    int j  = tid & 127;
    int ih = (tid >> 7) * 8;          // 8 i's per thread
    float acc[8];
#pragma unroll
    for (int k = 0; k < 8; k++) acc[k] = 0.0f;

    if (j < i0 + 16) {                // causally relevant j only
        const float* xp = g_x1T + b * (HH * TT) + j;
        for (int h = 0; h < HH; h++) {
            float x1v = xp[h * TT] * 0.5f;
            float wv = w0s[h];
#pragma unroll
            for (int k = 0; k < 8; k++) {
                float t = ftanh(x1v + qh[ih + k][h]);
                acc[k] = fmaf(wv, t, acc[k]);
            }
        }
    }
#pragma unroll
    for (int k = 0; k < 8; k++) {
        int ig = i0 + ih + k;
        ssh[ih + k][j] = (j <= ig) ? 0.5f * (acc[k] + w0sum) : 0.0f;
    }
    __syncthreads();

    // ---- phase 2: m_a ----
    int h   = tid & 127;
    int ih2 = (tid >> 7) * 8;
    float m[8];
#pragma unroll
    for (int k = 0; k < 8; k++) m[k] = 0.0f;

    const float* ip = in + b * HH + h;
    int jmax = i0 + 16;
    for (int jj = 0; jj < jmax; jj += 4) {
        float v0 = ip[(jj + 0) * (BB*HH)];
        float v1 = ip[(jj + 1) * (BB*HH)];
        float v2 = ip[(jj + 2) * (BB*HH)];
        float v3 = ip[(jj + 3) * (BB*HH)];
#pragma unroll
        for (int k = 0; k < 8; k++) {
            float4 s4 = *(const float4*)&ssh[ih2 + k][jj];
            m[k] = fmaf(s4.x, v0, fmaf(s4.y, v1, fmaf(s4.z, v2, fmaf(s4.w, v3, m[k]))));
        }
    }
#pragma unroll
    for (int k = 0; k < 8; k++)
        g_ma[((i0 + ih2 + k) * BB + b) * HH + h] = m[k];
}

// ---------------------------------------------------------------------------
// K4: predict heads. 32 rows/block, grid (256, 2): blockIdx.y = pass (c / v).
// Weight LDGs SOFTWARE-PIPELINED (double-buffered): prefetch chunk hb+4
// while computing chunk hb, so the ~262cyc L2 latency is hidden in-warp.
// ---------------------------------------------------------------------------
__global__ __launch_bounds__(256) void k_predict(
    const float* __restrict__ in,
    const float* __restrict__ c0a, const float* __restrict__ c0ab,
    const float* __restrict__ c0b, const float* __restrict__ c0bb,
    const float* __restrict__ c1a, const float* __restrict__ c1ab,
    const float* __restrict__ c1b, const float* __restrict__ c1bb,
    const float* __restrict__ v0a, const float* __restrict__ v0ab,
    const float* __restrict__ v0b, const float* __restrict__ v0bb,
    const float* __restrict__ v1a, const float* __restrict__ v1ab,
    const float* __restrict__ v1b, const float* __restrict__ v1bb,
    float* __restrict__ out)
{
    __shared__ float sbuf[2][HH][36];   // inputs -> layer0 acts -> layer1 outs
    const int ROWS = 32;
    int tid    = threadIdx.x;
    int row0   = blockIdx.x * ROWS;
    int pass   = blockIdx.y;
    int branch = tid >> 7;              // 0: a-side (m_a), 1: b-side (inputs)
    int t7     = tid & 127;

    const float *k0, *k0bias, *k1, *k1bias;
    if (pass == 0) { k0 = branch ? c0b : c0a; k0bias = branch ? c0bb : c0ab;
                     k1 = branch ? c1b : c1a; k1bias = branch ? c1bb : c1ab; }
    else           { k0 = branch ? v0b : v0a; k0bias = branch ? v0bb : v0ab;
                     k1 = branch ? v1b : v1a; k1bias = branch ? v1bb : v1ab; }

    // ---- load inputs transposed [h][row] ----
    for (int idx = tid; idx < ROWS * HH; idx += 256) {
        int h = idx & 127, r = idx >> 7;
        sbuf[0][h][r] = g_ma[(row0 + r) * HH + h];
        sbuf[1][h][r] = in[(row0 + r) * HH + h];
    }
    __syncthreads();

    // ---- layer 0: [32,128] x [128,128] per branch, 4 cols x 8 rows/thread --
    int cg = t7 & 31;               // cols cg*4 .. cg*4+3
    int rg = t7 >> 5;               // rows rg*8 .. rg*8+7
    float a0[32];
#pragma unroll
    for (int x = 0; x < 32; x++) a0[x] = 0.0f;

    {
        const float4* wp = (const float4*)(k0 + cg * 4);   // stride EE0/4 float4s
        float4 wbuf[4];
#pragma unroll
        for (int k = 0; k < 4; k++) wbuf[k] = wp[k * (EE0/4)];
        for (int hb = 0; hb < HH; hb += 4) {
            float4 w[4];
#pragma unroll
            for (int k = 0; k < 4; k++) w[k] = wbuf[k];
            if (hb + 4 < HH) {
#pragma unroll
                for (int k = 0; k < 4; k++)
                    wbuf[k] = wp[(hb + 4 + k) * (EE0/4)];
            }
#pragma unroll
            for (int k = 0; k < 4; k++) {
                float4 va = *(const float4*)&sbuf[branch][hb + k][rg * 8];
                float4 vb = *(const float4*)&sbuf[branch][hb + k][rg * 8 + 4];
                float wv[4] = {w[k].x, w[k].y, w[k].z, w[k].w};
                float rv[8] = {va.x, va.y, va.z, va.w, vb.x, vb.y, vb.z, vb.w};
#pragma unroll
                for (int cc = 0; cc < 4; cc++)
#pragma unroll
                    for (int rr = 0; rr < 8; rr++)
                        a0[cc * 8 + rr] = fmaf(wv[cc], rv[rr], a0[cc * 8 + rr]);
            }
        }
    }
    float4 b0v = *(const float4*)&k0bias[cg * 4];
    float b0[4] = {b0v.x, b0v.y, b0v.z, b0v.w};
    __syncthreads();   // all reads of sbuf inputs done
#pragma unroll
    for (int cc = 0; cc < 4; cc++) {
        float t0[8];
#pragma unroll
        for (int rr = 0; rr < 8; rr++) t0[rr] = leakyf_(a0[cc * 8 + rr] + b0[cc]);
        float* dst = &sbuf[branch][cg * 4 + cc][rg * 8];
        *(float4*)(dst)     = make_float4(t0[0], t0[1], t0[2], t0[3]);
        *(float4*)(dst + 4) = make_float4(t0[4], t0[5], t0[6], t0[7]);
    }
    __syncthreads();

    // ---- layer 1: [32,128] x [128,64] per branch, 4 cols x 4 rows/thread --
    int cg2 = t7 & 15;              // cols cg2*4 of 64
    int rg2 = t7 >> 4;              // rows rg2*4 of 32
    float a1[16];
#pragma unroll
    for (int x = 0; x < 16; x++) a1[x] = 0.0f;

    {
        const float4* wp = (const float4*)(k1 + cg2 * 4);  // stride EE1/4 float4s
        float4 wbuf[4];
#pragma unroll
        for (int k = 0; k < 4; k++) wbuf[k] = wp[k * (EE1/4)];
        for (int hb = 0; hb < EE0; hb += 4) {
            float4 w[4];
#pragma unroll
            for (int k = 0; k < 4; k++) w[k] = wbuf[k];
            if (hb + 4 < EE0) {
#pragma unroll
                for (int k = 0; k < 4; k++)
                    wbuf[k] = wp[(hb + 4 + k) * (EE1/4)];
            }
#pragma unroll
            for (int k = 0; k < 4; k++) {
                float4 v4 = *(const float4*)&sbuf[branch][hb + k][rg2 * 4];
                float wv[4] = {w[k].x, w[k].y, w[k].z, w[k].w};
                float rv[4] = {v4.x, v4.y, v4.z, v4.w};
#pragma unroll
                for (int cc = 0; cc < 4; cc++)
#pragma unroll
                    for (int rr = 0; rr < 4; rr++)
                        a1[cc * 4 + rr] = fmaf(wv[cc], rv[rr], a1[cc * 4 + rr]);
            }
        }
    }
    float4 b1v = *(const float4*)&k1bias[cg2 * 4];
    float b1[4] = {b1v.x, b1v.y, b1v.z, b1v.w};
    __syncthreads();   // all reads of layer0 acts done

    // write activated layer1 outputs into reused sbuf: [branch*32+row][68]
    float* sl1 = &sbuf[0][0][0];
#pragma unroll
    for (int rr = 0; rr < 4; rr++) {
        int row = rg2 * 4 + rr;
        float4 v = make_float4(leakyf_(a1[0 * 4 + rr] + b1[0]),
                               leakyf_(a1[1 * 4 + rr] + b1[1]),
                               leakyf_(a1[2 * 4 + rr] + b1[2]),
                               leakyf_(a1[3 * 4 + rr] + b1[3]));
        *(float4*)&sl1[(branch * 32 + row) * 68 + cg2 * 4] = v;
    }
    __syncthreads();

    // ---- product + reduce + sigmoid ----
    int row = tid >> 3;             // 0..31
    int lg  = tid & 7;              // 8 lanes per row, 8 elems each
    const float* pa = &sl1[(0 * 32 + row) * 68 + lg * 8];
    const float* pb = &sl1[(1 * 32 + row) * 68 + lg * 8];
    float4 a4 = *(const float4*)pa, a5 = *(const float4*)(pa + 4);
    float4 b4 = *(const float4*)pb, b5 = *(const float4*)(pb + 4);
    float p = a4.x*b4.x + a4.y*b4.y + a4.z*b4.z + a4.w*b4.w
            + a5.x*b5.x + a5.y*b5.y + a5.z*b5.z + a5.w*b5.w;
    p += __shfl_xor_sync(0xFFFFFFFFu, p, 4);
    p += __shfl_xor_sync(0xFFFFFFFFu, p, 2);
    p += __shfl_xor_sync(0xFFFFFFFFu, p, 1);
    if (lg == 0)
        out[pass * TB + row0 + row] = sigmoidf_(p);
}

// ---------------------------------------------------------------------------
// K5: out[TB+i] *= out[i]  (pv = raw_pv * pc)
// ---------------------------------------------------------------------------
__global__ __launch_bounds__(256) void k_mul(float* __restrict__ out) {
    int i = blockIdx.x * 256 + threadIdx.x;
    out[TB + i] *= out[i];
}

// ---------------------------------------------------------------------------
extern "C" void kernel_launch(void* const* d_in, const int* in_sizes, int n_in,
                              void* d_out, int out_size)
{
    (void)in_sizes; (void)n_in; (void)out_size;
    const float* in_  = (const float*)d_in[0];
    const float* w1k  = (const float*)d_in[1];
    const float* w1b  = (const float*)d_in[2];
    const float* w2k  = (const float*)d_in[3];
    const float* w3k  = (const float*)d_in[4];
    const float* w0k  = (const float*)d_in[5];
    const float* pc0a = (const float*)d_in[6];
    const float* pc0ab= (const float*)d_in[7];
    const float* pc0b = (const float*)d_in[8];
    const float* pc0bb= (const float*)d_in[9];
    const float* pc1a = (const float*)d_in[10];
    const float* pc1ab= (const float*)d_in[11];
    const float* pc1b = (const float*)d_in[12];
    const float* pc1bb= (const float*)d_in[13];
    const float* pv0a = (const float*)d_in[14];
    const float* pv0ab= (const float*)d_in[15];
    const float* pv0b = (const float*)d_in[16];
    const float* pv0bb= (const float*)d_in[17];
    const float* pv1a = (const float*)d_in[18];
    const float* pv1ab= (const float*)d_in[19];
    const float* pv1b = (const float*)d_in[20];
    const float* pv1bb= (const float*)d_in[21];
    float* out = (float*)d_out;

    k_cumsum<<<BB*HH/128, 128>>>(in_);
    k_gemm1<<<TB/32, 256>>>(in_, w1k, w1b, w2k, w3k);
    k_scores<<<dim3(TT/16, BB), 256>>>(in_, w0k);
    k_predict<<<dim3(TB/32, 2), 256>>>(in_,
        pc0a, pc0ab, pc0b, pc0bb, pc1a, pc1ab, pc1b, pc1bb,
        pv0a, pv0ab, pv0b, pv0bb, pv1a, pv1ab, pv1b, pv1bb,
        out);
    k_mul<<<TB/256, 256>>>(out);
}